// round 1
// baseline (speedup 1.0000x reference)
#include <cuda_runtime.h>
#include <cstdint>

#define DI __device__ __forceinline__

// ---------- packed f32x2 helpers (FFMA2 is PTX-only on sm_103a) ----------
DI unsigned long long pack2(float lo, float hi) {
    unsigned long long r;
    asm("mov.b64 %0, {%1, %2};"
        : "=l"(r) : "r"(__float_as_uint(lo)), "r"(__float_as_uint(hi)));
    return r;
}
DI void unpack2(unsigned long long v, float& lo, float& hi) {
    unsigned lo_, hi_;
    asm("mov.b64 {%0, %1}, %2;" : "=r"(lo_), "=r"(hi_) : "l"(v));
    lo = __uint_as_float(lo_);
    hi = __uint_as_float(hi_);
}
DI unsigned long long fma2(unsigned long long a, unsigned long long b, unsigned long long c) {
    unsigned long long d;
    asm("fma.rn.f32x2 %0, %1, %2, %3;" : "=l"(d) : "l"(a), "l"(b), "l"(c));
    return d;
}
DI unsigned long long mul2(unsigned long long a, unsigned long long b) {
    unsigned long long d;
    asm("mul.rn.f32x2 %0, %1, %2;" : "=l"(d) : "l"(a), "l"(b));
    return d;
}

// v if z > 0 else 0   (sign-bit trick: SHF + LOP3, alu pipe, no FSETP)
DI float sel_pos(float z, float v) {
    int s = __float_as_int(z) >> 31;               // 0 or -1
    return __int_as_float(__float_as_int(v) & ~s);
}
// g if h > 0 else 0, where h = relu(z) >= 0  (h==+0 -> zero out)
DI float mask_relu(float h, float g) {
    int m = (__float_as_int(h) - 1) >> 31;         // -1 iff h == +0
    return __int_as_float(__float_as_int(g) & ~m);
}

__global__ void __launch_bounds__(128, 3) toy_force_kernel(
    const float4* __restrict__ pos,   // npairs float4 = 2 positions each
    const float*  __restrict__ W1,    // [8,2]
    const float*  __restrict__ b1,    // [8]
    const float*  __restrict__ W2,    // [4,8]
    const float*  __restrict__ b2,    // [4]
    const float*  __restrict__ W3,    // [2,4]
    float4*       __restrict__ out,   // npairs float4 = 2 forces each
    int npairs)
{
    // ---- hoist weights once per thread, pre-packed (w,w) for f32x2 ----
    unsigned long long w1x[8], w1y[8], B1[8], w2p[4][8], B2[4];
    float v3n[4];
#pragma unroll
    for (int i = 0; i < 8; i++) {
        float a = __ldg(&W1[2 * i]);
        float b = __ldg(&W1[2 * i + 1]);
        float c = __ldg(&b1[i]);
        w1x[i] = pack2(a, a);
        w1y[i] = pack2(b, b);
        B1[i]  = pack2(c, c);
    }
#pragma unroll
    for (int j = 0; j < 4; j++) {
#pragma unroll
        for (int i = 0; i < 8; i++) {
            float w = __ldg(&W2[8 * j + i]);
            w2p[j][i] = pack2(w, w);
        }
        float bb = __ldg(&b2[j]);
        B2[j] = pack2(bb, bb);
        // fold the final negation into v3:  f = -W1^T g1  ==> flip v3 sign
        v3n[j] = -(__ldg(&W3[j]) + __ldg(&W3[4 + j]));
    }

    const int stride = gridDim.x * blockDim.x;
    int k = blockIdx.x * blockDim.x + threadIdx.x;
    if (k >= npairs) return;

    float4 p = pos[k];
    while (true) {
        const int kn = k + stride;
        const bool more = kn < npairs;
        float4 pn;
        if (more) pn = pos[kn];      // prefetch next iteration's positions

        const unsigned long long PX = pack2(p.x, p.z);
        const unsigned long long PY = pack2(p.y, p.w);

        // ---- layer 1: z1 = W1 p + b1 ; h1 = relu(z1)  (16 f32x2 FMA) ----
        unsigned long long h1[8];
#pragma unroll
        for (int i = 0; i < 8; i++) {
            unsigned long long z = fma2(w1x[i], PX, fma2(w1y[i], PY, B1[i]));
            float lo, hi;
            unpack2(z, lo, hi);
            h1[i] = pack2(fmaxf(lo, 0.f), fmaxf(hi, 0.f));
        }

        // ---- layer 2: z2 = W2 h1 + b2 ; g2 = 1[z2>0] * (-v3)  (32 f32x2 FMA) ----
        unsigned long long g2[4];
#pragma unroll
        for (int j = 0; j < 4; j++) {
            unsigned long long z = B2[j];
#pragma unroll
            for (int i = 0; i < 8; i++) z = fma2(w2p[j][i], h1[i], z);
            float lo, hi;
            unpack2(z, lo, hi);
            g2[j] = pack2(sel_pos(lo, v3n[j]), sel_pos(hi, v3n[j]));
        }

        // ---- backward: g1 = 1[z1>0] * (W2^T g2) ; f = W1^T g1  (48 f32x2) ----
        unsigned long long fx = 0ull, fy = 0ull;  // packed (+0,+0)
#pragma unroll
        for (int i = 0; i < 8; i++) {
            unsigned long long g = mul2(w2p[0][i], g2[0]);
            g = fma2(w2p[1][i], g2[1], g);
            g = fma2(w2p[2][i], g2[2], g);
            g = fma2(w2p[3][i], g2[3], g);
            float glo, ghi, hlo, hhi;
            unpack2(g, glo, ghi);
            unpack2(h1[i], hlo, hhi);
            const unsigned long long gm =
                pack2(mask_relu(hlo, glo), mask_relu(hhi, ghi));
            fx = fma2(w1x[i], gm, fx);
            fy = fma2(w1y[i], gm, fy);
        }

        float fxl, fxh, fyl, fyh;
        unpack2(fx, fxl, fxh);
        unpack2(fy, fyl, fyh);
        out[k] = make_float4(fxl, fyl, fxh, fyh);

        if (!more) break;
        k = kn;
        p = pn;
    }
}

extern "C" void kernel_launch(void* const* d_in, const int* in_sizes, int n_in,
                              void* d_out, int out_size) {
    const float* pos = (const float*)d_in[0];
    const float* W1  = (const float*)d_in[1];
    const float* b1  = (const float*)d_in[2];
    const float* W2  = (const float*)d_in[3];
    const float* b2  = (const float*)d_in[4];
    const float* W3  = (const float*)d_in[5];
    float* out = (float*)d_out;

    // in_sizes[0] = N*2 floats; each float4 covers 2 positions
    const int npairs = in_sizes[0] / 4;

    const int threads = 128;
    const int blocks  = 1184;   // 148 SMs x 8, grid-stride loop balances
    toy_force_kernel<<<blocks, threads>>>(
        (const float4*)pos, W1, b1, W2, b2, W3, (float4*)out, npairs);
}

// round 2
// speedup vs baseline: 1.0111x; 1.0111x over previous
#include <cuda_runtime.h>

typedef unsigned long long u64;
#define DI __device__ __forceinline__

// ---------- packed f32x2 helpers (FFMA2 is PTX-only on sm_103a) ----------
DI u64 pack2(float lo, float hi) {
    u64 r;
    asm("mov.b64 %0, {%1, %2};"
        : "=l"(r) : "r"(__float_as_uint(lo)), "r"(__float_as_uint(hi)));
    return r;
}
DI void unpack2(u64 v, unsigned& lo, unsigned& hi) {
    asm("mov.b64 {%0, %1}, %2;" : "=r"(lo), "=r"(hi) : "l"(v));
}
DI u64 fma2(u64 a, u64 b, u64 c) {
    u64 d;
    asm("fma.rn.f32x2 %0, %1, %2, %3;" : "=l"(d) : "l"(a), "l"(b), "l"(c));
    return d;
}

struct Weights {
    u64 w1x[8], w1y[8], B1[8];
    u64 w2p[4][8], B2[4];
};

// Evaluate force for one float4 (two 2-D positions) via forward-pass signs +
// 4096-entry force table (byte-offset indexed: logical entry e at offset 8e).
DI float4 eval(const float4 p, const Weights& W, const char* __restrict__ tab) {
    const u64 PX = pack2(p.x, p.z);
    const u64 PY = pack2(p.y, p.w);

    u64 h1[8];
    unsigned ilo = 0, ihi = 0;
#pragma unroll
    for (int i = 0; i < 8; i++) {
        u64 z = fma2(W.w1x[i], PX, fma2(W.w1y[i], PY, W.B1[i]));
        unsigned zl, zh;
        unpack2(z, zl, zh);
        ilo |= ((unsigned)((int)zl >> 31)) & (8u << i);     // bit set <=> z1_i < 0 (inactive)
        ihi |= ((unsigned)((int)zh >> 31)) & (8u << i);
        h1[i] = pack2(fmaxf(__uint_as_float(zl), 0.f),
                      fmaxf(__uint_as_float(zh), 0.f));
    }
#pragma unroll
    for (int j = 0; j < 4; j++) {
        u64 acc = W.B2[j];
#pragma unroll
        for (int i = 0; i < 8; i++) acc = fma2(W.w2p[j][i], h1[i], acc);
        unsigned zl, zh;
        unpack2(acc, zl, zh);
        ilo |= ((unsigned)((int)zl >> 31)) & (2048u << j);  // logical bit 8+j
        ihi |= ((unsigned)((int)zh >> 31)) & (2048u << j);
    }
    const float2 flo = *(const float2*)(tab + ilo);
    const float2 fhi = *(const float2*)(tab + ihi);
    return make_float4(flo.x, flo.y, fhi.x, fhi.y);
}

__global__ void __launch_bounds__(128, 4) toy_force_kernel(
    const float4* __restrict__ pos,
    const float*  __restrict__ W1,   // [8,2]
    const float*  __restrict__ b1,   // [8]
    const float*  __restrict__ W2,   // [4,8]
    const float*  __restrict__ b2,   // [4]
    const float*  __restrict__ W3,   // [2,4]
    float4*       __restrict__ out,
    int npairs)
{
    __shared__ float  u_s[16][8];     // u(m2)_i = sum_{j active} (-v3_j) * W2[j][i]
    __shared__ float2 ftab[4096];     // force per (m1,m2) sign pattern

    const int tid = threadIdx.x;

    // ---- build u table (128 threads: one (m2, i) each) ----
    {
        const int i = tid & 7, m = tid >> 3;   // m in [0,16)
        float s = 0.f;
#pragma unroll
        for (int j = 0; j < 4; j++) {
            float v3n = -(__ldg(&W3[j]) + __ldg(&W3[4 + j]));  // fold final negation
            if (!((m >> j) & 1)) s += v3n * __ldg(&W2[8 * j + i]);
        }
        u_s[m][i] = s;
    }
    __syncthreads();

    // ---- build 4096-entry force table: f = sum_{i: m1 bit clear} u_i * W1[i,:] ----
    {
        float w1c[16];
#pragma unroll
        for (int t = 0; t < 16; t++) w1c[t] = __ldg(&W1[t]);
        for (int e = tid; e < 4096; e += blockDim.x) {
            const int m2 = e >> 8;
            float fx = 0.f, fy = 0.f;
#pragma unroll
            for (int i = 0; i < 8; i++) {
                const float msk = ((e >> i) & 1) ? 0.f : 1.f;
                const float ui = msk * u_s[m2][i];
                fx = fmaf(ui, w1c[2 * i], fx);
                fy = fmaf(ui, w1c[2 * i + 1], fy);
            }
            ftab[e] = make_float2(fx, fy);
        }
    }

    // ---- hoist packed weights for the streaming loop ----
    Weights W;
#pragma unroll
    for (int i = 0; i < 8; i++) {
        const float a = __ldg(&W1[2 * i]);
        const float b = __ldg(&W1[2 * i + 1]);
        const float c = __ldg(&b1[i]);
        W.w1x[i] = pack2(a, a);
        W.w1y[i] = pack2(b, b);
        W.B1[i]  = pack2(c, c);
    }
#pragma unroll
    for (int j = 0; j < 4; j++) {
#pragma unroll
        for (int i = 0; i < 8; i++) {
            const float w = __ldg(&W2[8 * j + i]);
            W.w2p[j][i] = pack2(w, w);
        }
        const float bb = __ldg(&b2[j]);
        W.B2[j] = pack2(bb, bb);
    }
    __syncthreads();

    const char* tab = (const char*)ftab;
    const int stride = gridDim.x * blockDim.x;

    // ---- grid-stride, ILP=2, rotating double prefetch ----
    int ka = blockIdx.x * blockDim.x + tid;
    if (ka >= npairs) return;
    int kb = ka + stride;
    bool hb = kb < npairs;

    float4 pa = pos[ka];
    float4 pb = hb ? pos[kb] : pa;

    while (true) {
        const int kan = ka + 2 * stride;
        const int kbn = kb + 2 * stride;
        const bool han = kan < npairs;
        const bool hbn = hb && (kbn < npairs);
        float4 na, nb;
        if (han) na = pos[kan];          // prefetch next pair of tiles
        if (hbn) nb = pos[kbn];

        out[ka] = eval(pa, W, tab);
        if (hb) out[kb] = eval(pb, W, tab);

        if (!han) break;
        pa = na;
        pb = hbn ? nb : na;
        ka = kan;
        kb = kbn;
        hb = hbn;
    }
}

extern "C" void kernel_launch(void* const* d_in, const int* in_sizes, int n_in,
                              void* d_out, int out_size) {
    const float* pos = (const float*)d_in[0];
    const float* W1  = (const float*)d_in[1];
    const float* b1  = (const float*)d_in[2];
    const float* W2  = (const float*)d_in[3];
    const float* b2  = (const float*)d_in[4];
    const float* W3  = (const float*)d_in[5];
    float* out = (float*)d_out;

    const int npairs = in_sizes[0] / 4;   // float4 = 2 positions

    const int threads = 128;
    const int blocks  = 592;              // 148 SMs x 4 CTAs
    toy_force_kernel<<<blocks, threads>>>(
        (const float4*)pos, W1, b1, W2, b2, W3, (float4*)out, npairs);
}